// round 9
// baseline (speedup 1.0000x reference)
#include <cuda_runtime.h>

// Problem constants: B=512, K=512, U=3, L=32, H=128, n_gate_rows=384
#define NK      512
#define NBATCH  512
#define HN      128
#define LN      32
#define NROW    384
#define GB      4      // batches per block
#define TPB     512
#define THETA_LO    0.001f
#define THETA_RANGE 1.999f

// dynamic smem layout (float offsets)
#define OFF_WHH 0                    // 384*128 = 49152 floats, pair-layout [j4][row]
#define OFF_AR  49152                // [g*128+i] r-gate preact (gx+gh)
#define OFF_AZ  (OFF_AR + 512)
#define OFF_AXN (OFF_AZ + 512)
#define OFF_AHN (OFF_AXN + 512)
#define OFF_H   (OFF_AHN + 512)      // 2 bufs * 32 j4 * 4 g * float4 = 1024 floats
#define OFF_LF  (OFF_H + 1024)       // 8 j4 * 4 g * float4 = 128 floats
#define SMEM_FLOATS (OFF_LF + 128)   // 52352 floats = 209408 B

#define HIDX(buf,i,g) (((((buf)*32) + ((i)>>2))*4 + (g))*4 + ((i)&3))

// ---- XLA/Eigen FastTanh (exact algorithm XLA lowers f32 tanh to) ----
__device__ __forceinline__ float xla_tanh(float x){
    const float kHi = 7.90531110763549805f;
    float xc = fmaxf(fminf(x, kHi), -kHi);
    float x2 = __fmul_rn(xc, xc);
    float p = fmaf(x2, -2.76076847742355e-16f, 2.00018790482477e-13f);
    p = fmaf(x2, p, -8.60467152213735e-11f);
    p = fmaf(x2, p,  5.12229709037114e-08f);
    p = fmaf(x2, p,  1.48572235717979e-05f);
    p = fmaf(x2, p,  6.37261928875436e-04f);
    p = fmaf(x2, p,  4.89352455891786e-03f);
    p = __fmul_rn(xc, p);
    float q = fmaf(x2, 1.19825839466702e-06f, 1.18534705686654e-04f);
    q = fmaf(x2, q, 2.26843463243900e-03f);
    q = fmaf(x2, q, 4.89352518554385e-03f);
    float r = __fdiv_rn(p, q);
    return (fabsf(x) < 0.0004f) ? x : r;
}
__device__ __forceinline__ float sigx(float x){
    float t = xla_tanh(__fmul_rn(0.5f, x));
    return __fadd_rn(0.5f, __fmul_rn(0.5f, t));
}

// ---- packed f32x2 helpers ----
__device__ __forceinline__ float2 unpack2(unsigned long long v){
    float2 r;
    asm("mov.b64 {%0, %1}, %2;" : "=f"(r.x), "=f"(r.y) : "l"(v));
    return r;
}
__device__ __forceinline__ void ffma2(unsigned long long& d,
                                      unsigned long long a,
                                      unsigned long long b){
    asm("fma.rn.f32x2 %0, %1, %2, %0;" : "+l"(d) : "l"(a), "l"(b));
}

// de-fma'd 5-state kinetics rhs (matches jnp elementwise)
#define RHS(A,B,C,D,E, dA,dB,dC,dD,dE) {                                 \
    float r1 = __fmul_rn(__fmul_rn(k1p,(A)),(B));                        \
    float r2 = __fmul_rn(k2p,(C));                                       \
    float r3 = __fmul_rn(__fmul_rn(k3p,(C)),(D));                        \
    float r4 = __fmul_rn(k4p,(E));                                       \
    float r5 = __fmul_rn(k5p,(A));                                       \
    dA = __fsub_rn(-r1, r5);                                             \
    dB = __fadd_rn(-r1, r2);                                             \
    dC = __fsub_rn(__fsub_rn(r1, r2), r3);                               \
    dD = __fadd_rn(-r3, r4);                                             \
    dE = __fadd_rn(__fsub_rn(r3, r4), r5); }
#define AXPY(y, c, k) __fadd_rn((y), __fmul_rn((c), (k)))

__global__ void __launch_bounds__(TPB, 1) kin_rnn_kernel(
    const float* __restrict__ y0,      // (512,3)
    const float* __restrict__ u_seq,   // (512,512,3)
    const float* __restrict__ dt_seq,  // (512,512)
    const float* __restrict__ y_seq,   // (512,512,3)
    const float* __restrict__ W_lift,  // (32,6)
    const float* __restrict__ b_lift,  // (32)
    const float* __restrict__ W_ih,    // (384,32)
    const float* __restrict__ W_hh,    // (384,128)
    const float* __restrict__ b_ih,    // (384)
    const float* __restrict__ b_hh,    // (384)
    const float* __restrict__ W_head,  // (5,128)
    const float* __restrict__ b_head,  // (5)
    const float* __restrict__ Jm,      // (3,3)
    float* __restrict__ out)
{
    extern __shared__ float smem[];
    const int tid  = threadIdx.x;
    const int lane = tid & 31;
    const int wid  = tid >> 5;

    ulonglong2* sWhh = (ulonglong2*)(smem + OFF_WHH);     // [j4*384 + row]
    float* sAr  = smem + OFF_AR;
    float* sAz  = smem + OFF_AZ;
    float* sAxn = smem + OFF_AXN;
    float* sAhn = smem + OFF_AHN;
    float* sH   = smem + OFF_H;

    const bool isDot = (tid >= 128);
    const int  row   = tid - 128;          // valid when isDot

    // ---- init: W_hh into pair-layout shared, zero h buffers ----
    if (isDot) {
        const ulonglong2* src = (const ulonglong2*)(W_hh + row * HN);
#pragma unroll 8
        for (int j4 = 0; j4 < 32; j4++) sWhh[j4 * NROW + row] = src[j4];
    }
    for (int p = tid; p < 1024; p += TPB) sH[p] = 0.f;

    // ---- per-role constants ----
    unsigned long long wih[16];     // dot: own W_ih row as f32x2 pairs
    float bih = 0.f, bhh = 0.f;
    float wl0=0,wl1=0,wl2=0,wl3=0,wl4=0,wl5=0, blf=0;
    float whd[20];                  // batch: W_head[j][4*lane..+3]
    float bhsel = 0.f;
    float J00=0,J01=0,J02=0,J10=0,J11=0,J12=0,J20=0,J21=0,J22=0;
    float yA=0,yB=0,yC=0,yD=0,yE=0;
    float uc0=0,uc1=0,uc2=0,dtc=0, up0=0,up1=0,up2=0,dtp=0;
    float tf0=0,tf1=0,tf2=0;
    const float* gu = nullptr; const float* gdt = nullptr; const float* gy = nullptr;
    float* yo = nullptr; float* to = nullptr;

    if (isDot) {
        const ulonglong2* s = (const ulonglong2*)(W_ih + row * LN);
#pragma unroll
        for (int j = 0; j < 8; j++) { ulonglong2 v = s[j]; wih[2*j] = v.x; wih[2*j+1] = v.y; }
        bih = b_ih[row]; bhh = b_hh[row];
    } else {
        const int g = wid;                        // 0..3
        const int b = blockIdx.x * GB + g;
        wl0 = W_lift[lane*6+0]; wl1 = W_lift[lane*6+1]; wl2 = W_lift[lane*6+2];
        wl3 = W_lift[lane*6+3]; wl4 = W_lift[lane*6+4]; wl5 = W_lift[lane*6+5];
        blf = b_lift[lane];
#pragma unroll
        for (int j = 0; j < 5; j++)
#pragma unroll
            for (int c = 0; c < 4; c++) whd[j*4+c] = W_head[j*HN + lane*4 + c];
        bhsel = b_head[(lane < 5) ? lane : 0];
        J00 = Jm[0]; J01 = Jm[1]; J02 = Jm[2];
        J10 = Jm[3]; J11 = Jm[4]; J12 = Jm[5];
        J20 = Jm[6]; J21 = Jm[7]; J22 = Jm[8];
        yA = y0[b*3+0]; yC = y0[b*3+1]; yE = y0[b*3+2]; yB = 0.f; yD = 0.f;
        gu = u_seq + (size_t)b * NK * 3;
        gdt = dt_seq + (size_t)b * NK;
        gy  = y_seq + (size_t)b * NK * 3;
        yo  = out + (size_t)b * NK * 3;
        to  = out + (size_t)NBATCH * NK * 3 + (size_t)b * NK * 5;
        uc0 = gu[0]; uc1 = gu[1]; uc2 = gu[2]; dtc = gdt[0];
    }
    __syncthreads();

    // batch-warp tail: theta_{kout} + y_jump + RK4_{kout} + outputs_{kout}
    auto tail = [&](int hb, int kout) {
        const int g = wid;
        // h_new[4*lane .. 4*lane+3] of batch g
        float4 h4 = ((const float4*)sH)[(hb*32 + lane)*4 + g];
        float t0 = __fmul_rn(whd[0],  h4.x); t0 = fmaf(whd[1],  h4.y, t0);
        t0 = fmaf(whd[2],  h4.z, t0);        t0 = fmaf(whd[3],  h4.w, t0);
        float t1 = __fmul_rn(whd[4],  h4.x); t1 = fmaf(whd[5],  h4.y, t1);
        t1 = fmaf(whd[6],  h4.z, t1);        t1 = fmaf(whd[7],  h4.w, t1);
        float t2 = __fmul_rn(whd[8],  h4.x); t2 = fmaf(whd[9],  h4.y, t2);
        t2 = fmaf(whd[10], h4.z, t2);        t2 = fmaf(whd[11], h4.w, t2);
        float t3 = __fmul_rn(whd[12], h4.x); t3 = fmaf(whd[13], h4.y, t3);
        t3 = fmaf(whd[14], h4.z, t3);        t3 = fmaf(whd[15], h4.w, t3);
        float t4 = __fmul_rn(whd[16], h4.x); t4 = fmaf(whd[17], h4.y, t4);
        t4 = fmaf(whd[18], h4.z, t4);        t4 = fmaf(whd[19], h4.w, t4);
#pragma unroll
        for (int m = 16; m >= 1; m >>= 1) {
            t0 = __fadd_rn(t0, __shfl_xor_sync(0xffffffffu, t0, m));
            t1 = __fadd_rn(t1, __shfl_xor_sync(0xffffffffu, t1, m));
            t2 = __fadd_rn(t2, __shfl_xor_sync(0xffffffffu, t2, m));
            t3 = __fadd_rn(t3, __shfl_xor_sync(0xffffffffu, t3, m));
            t4 = __fadd_rn(t4, __shfl_xor_sync(0xffffffffu, t4, m));
        }
        float tsel = (lane == 0) ? t0 : (lane == 1) ? t1 :
                     (lane == 2) ? t2 : (lane == 3) ? t3 : t4;
        float ssel = sigx(__fadd_rn(tsel, bhsel));
        float ksel = __fadd_rn(THETA_LO, __fmul_rn(THETA_RANGE, ssel));
        float k1p = __shfl_sync(0xffffffffu, ksel, 0);
        float k2p = __shfl_sync(0xffffffffu, ksel, 1);
        float k3p = __shfl_sync(0xffffffffu, ksel, 2);
        float k4p = __shfl_sync(0xffffffffu, ksel, 3);
        float k5p = __shfl_sync(0xffffffffu, ksel, 4);

        // y_jump on observed dims (uses u_{kout} = up*)
        {
            float jA = __fmul_rn(up0, J00); jA = fmaf(up1, J10, jA); jA = fmaf(up2, J20, jA);
            float jC = __fmul_rn(up0, J01); jC = fmaf(up1, J11, jC); jC = fmaf(up2, J21, jC);
            float jE = __fmul_rn(up0, J02); jE = fmaf(up1, J12, jE); jE = fmaf(up2, J22, jE);
            yA = __fadd_rn(yA, jA); yC = __fadd_rn(yC, jC); yE = __fadd_rn(yE, jE);
        }
        // RK4 (n_sub=1)
        float hstep = dtp;
        float hh = __fmul_rn(0.5f, hstep);
        float d1A,d1B,d1C,d1D,d1E, d2A,d2B,d2C,d2D,d2E;
        float d3A,d3B,d3C,d3D,d3E, d4A,d4B,d4C,d4D,d4E;
        RHS(yA, yB, yC, yD, yE, d1A, d1B, d1C, d1D, d1E);
        {
            float tA = AXPY(yA, hh, d1A), tB = AXPY(yB, hh, d1B), tC = AXPY(yC, hh, d1C);
            float tD = AXPY(yD, hh, d1D), tE = AXPY(yE, hh, d1E);
            RHS(tA, tB, tC, tD, tE, d2A, d2B, d2C, d2D, d2E);
        }
        {
            float tA = AXPY(yA, hh, d2A), tB = AXPY(yB, hh, d2B), tC = AXPY(yC, hh, d2C);
            float tD = AXPY(yD, hh, d2D), tE = AXPY(yE, hh, d2E);
            RHS(tA, tB, tC, tD, tE, d3A, d3B, d3C, d3D, d3E);
        }
        {
            float tA = AXPY(yA, hstep, d3A), tB = AXPY(yB, hstep, d3B), tC = AXPY(yC, hstep, d3C);
            float tD = AXPY(yD, hstep, d3D), tE = AXPY(yE, hstep, d3E);
            RHS(tA, tB, tC, tD, tE, d4A, d4B, d4C, d4D, d4E);
        }
        float s6 = __fdiv_rn(hstep, 6.0f);
        #define RKSUM(d1,d2,d3,d4) \
            __fadd_rn(__fadd_rn(__fadd_rn((d1), __fmul_rn(2.0f,(d2))), __fmul_rn(2.0f,(d3))), (d4))
        yA = fmaxf(AXPY(yA, s6, RKSUM(d1A,d2A,d3A,d4A)), 0.f);
        yB = fmaxf(AXPY(yB, s6, RKSUM(d1B,d2B,d3B,d4B)), 0.f);
        yC = fmaxf(AXPY(yC, s6, RKSUM(d1C,d2C,d3C,d4C)), 0.f);
        yD = fmaxf(AXPY(yD, s6, RKSUM(d1D,d2D,d3D,d4D)), 0.f);
        yE = fmaxf(AXPY(yE, s6, RKSUM(d1E,d2E,d3E,d4E)), 0.f);
        #undef RKSUM

        if (lane < 3) {
            float ysel = (lane == 0) ? yA : ((lane == 1) ? yC : yE);
            yo[kout * 3 + lane] = ysel;
        }
        if (lane < 5) to[kout * 5 + lane] = ksel;
    };

    unsigned long long acc[4];   // gh accumulators (persist across SYNC_A)

    for (int k = 0; k < NK; k++) {
        const int hb = k & 1;
        if (isDot) {
            // ---- gh dot: h from broadcast LDS, own W_hh row streamed from smem ----
            acc[0] = 0ull; acc[1] = 0ull; acc[2] = 0ull; acc[3] = 0ull;
            const ulonglong2* sHb = (const ulonglong2*)sH + hb * 128;
#pragma unroll 8
            for (int j4 = 0; j4 < 32; j4++) {
                ulonglong2 wv = sWhh[j4 * NROW + row];
#pragma unroll
                for (int g = 0; g < 4; g++) {
                    ulonglong2 hv = sHb[j4 * 4 + g];
                    ffma2(acc[g], wv.x, hv.x);
                    ffma2(acc[g], wv.y, hv.y);
                }
            }
        } else {
            // ---- batch warp: finish step k-1, then lift for step k ----
            if (k > 0) tail(hb, k - 1);
            bool flag = (k > 0) && ((k % 50) == 0);
            float yi0 = flag ? tf0 : yA;
            float yi1 = flag ? tf1 : yC;
            float yi2 = flag ? tf2 : yE;
            float lv = __fmul_rn(wl0, uc0);
            lv = fmaf(wl1, uc1, lv);
            lv = fmaf(wl2, uc2, lv);
            lv = fmaf(wl3, yi0, lv);
            lv = fmaf(wl4, yi1, lv);
            lv = fmaf(wl5, yi2, lv);
            lv = __fadd_rn(lv, blf);
            lv = __fmul_rn(lv, sigx(lv));
            smem[OFF_LF + ((lane >> 2) * 4 + wid) * 4 + (lane & 3)] = lv;
            up0 = uc0; up1 = uc1; up2 = uc2; dtp = dtc;
        }
        __syncthreads();   // A: lift ready

        if (isDot) {
            // ---- gx dot (W_ih in regs, lift broadcast) + gate writes ----
            unsigned long long ax[4] = {0ull, 0ull, 0ull, 0ull};
            const ulonglong2* sLf2 = (const ulonglong2*)(smem + OFF_LF);
#pragma unroll
            for (int j4 = 0; j4 < 8; j4++) {
                unsigned long long w0 = wih[2*j4], w1 = wih[2*j4+1];
#pragma unroll
                for (int g = 0; g < 4; g++) {
                    ulonglong2 l = sLf2[j4 * 4 + g];
                    ffma2(ax[g], w0, l.x);
                    ffma2(ax[g], w1, l.y);
                }
            }
#pragma unroll
            for (int g = 0; g < 4; g++) {
                float2 ph = unpack2(acc[g]);
                float2 px = unpack2(ax[g]);
                float gh_s = __fadd_rn(__fadd_rn(ph.x, ph.y), bhh);
                float gx_s = __fadd_rn(__fadd_rn(px.x, px.y), bih);
                if (row < 128)      sAr[g*128 + row]        = __fadd_rn(gx_s, gh_s);
                else if (row < 256) sAz[g*128 + row - 128]  = __fadd_rn(gx_s, gh_s);
                else { sAxn[g*128 + row - 256] = gx_s; sAhn[g*128 + row - 256] = gh_s; }
            }
        } else {
            // ---- prefetch next step inputs ----
            if (k + 1 < NK) {
                uc0 = gu[3*(k+1)]; uc1 = gu[3*(k+1)+1]; uc2 = gu[3*(k+1)+2];
                dtc = gdt[k+1];
                if (((k + 1) % 50) == 0) { tf0 = gy[3*k]; tf1 = gy[3*k+1]; tf2 = gy[3*k+2]; }
            }
        }
        __syncthreads();   // B: gates ready

        // ---- GRU update: exactly one (g,i) task per thread ----
        {
            const int g = tid >> 7;
            const int i = tid & 127;
            float a_r = sAr[g*128 + i];
            float a_z = sAz[g*128 + i];
            float xn  = sAxn[g*128 + i];
            float hn  = sAhn[g*128 + i];
            float hold = sH[HIDX(hb, i, g)];
            float r = sigx(a_r);
            float z = sigx(a_z);
            float n = xla_tanh(__fadd_rn(xn, __fmul_rn(r, hn)));
            float hnew = __fadd_rn(__fmul_rn(__fsub_rn(1.0f, z), n), __fmul_rn(z, hold));
            sH[HIDX(1 - hb, i, g)] = hnew;
        }
        __syncthreads();   // C: h_new ready
    }

    // epilogue: step 511 tail (h_512 sits in buffer 0)
    if (!isDot) tail(0, NK - 1);
}

extern "C" void kernel_launch(void* const* d_in, const int* in_sizes, int n_in,
                              void* d_out, int out_size) {
    const float* y0     = (const float*)d_in[0];
    const float* u_seq  = (const float*)d_in[1];
    const float* dt_seq = (const float*)d_in[2];
    const float* y_seq  = (const float*)d_in[3];
    const float* W_lift = (const float*)d_in[4];
    const float* b_lift = (const float*)d_in[5];
    const float* W_ih   = (const float*)d_in[6];
    const float* W_hh   = (const float*)d_in[7];
    const float* b_ih   = (const float*)d_in[8];
    const float* b_hh   = (const float*)d_in[9];
    const float* W_head = (const float*)d_in[10];
    const float* b_head = (const float*)d_in[11];
    const float* Jm     = (const float*)d_in[12];
    float* out = (float*)d_out;

    const int smemBytes = SMEM_FLOATS * 4;   // 209408 B
    cudaFuncSetAttribute(kin_rnn_kernel,
                         cudaFuncAttributeMaxDynamicSharedMemorySize, smemBytes);
    // 128 blocks x 512 threads, 4 batches per block (warps 0-3 = batch warps,
    // warps 4-15 own one gate row each of [W_ih|W_hh])
    kin_rnn_kernel<<<NBATCH / GB, TPB, smemBytes>>>(
        y0, u_seq, dt_seq, y_seq, W_lift, b_lift,
        W_ih, W_hh, b_ih, b_hh, W_head, b_head, Jm, out);
}

// round 10
// speedup vs baseline: 1.2824x; 1.2824x over previous
#include <cuda_runtime.h>

// Problem constants: B=512, K=512, U=3, L=32, H=128, n_gate_rows=384
#define NK      512
#define NBATCH  512
#define HN      128
#define LN      32
#define NROW    384
#define GB      4      // batches per block
#define TPB     256    // warps 0-3: batch warps; warps 4-7: dot threads (128)
#define THETA_LO    0.001f
#define THETA_RANGE 1.999f

// dynamic smem layout (float offsets)
#define OFF_WHH 0                    // 384*128 floats, pair-layout [j4][row]
#define OFF_H   49152                // 2 bufs * 32 j4 * 4 g * float4 = 1024 floats
#define OFF_LF  (OFF_H + 1024)       // 8 j4 * 4 g * float4 = 128 floats
#define SMEM_FLOATS (OFF_LF + 128)   // 50304 floats = 201216 B

#define HIDX(buf,i,g) (((((buf)*32) + ((i)>>2))*4 + (g))*4 + ((i)&3))

// ---- XLA/Eigen FastTanh (exact algorithm XLA lowers f32 tanh to) ----
__device__ __forceinline__ float xla_tanh(float x){
    const float kHi = 7.90531110763549805f;
    float xc = fmaxf(fminf(x, kHi), -kHi);
    float x2 = __fmul_rn(xc, xc);
    float p = fmaf(x2, -2.76076847742355e-16f, 2.00018790482477e-13f);
    p = fmaf(x2, p, -8.60467152213735e-11f);
    p = fmaf(x2, p,  5.12229709037114e-08f);
    p = fmaf(x2, p,  1.48572235717979e-05f);
    p = fmaf(x2, p,  6.37261928875436e-04f);
    p = fmaf(x2, p,  4.89352455891786e-03f);
    p = __fmul_rn(xc, p);
    float q = fmaf(x2, 1.19825839466702e-06f, 1.18534705686654e-04f);
    q = fmaf(x2, q, 2.26843463243900e-03f);
    q = fmaf(x2, q, 4.89352518554385e-03f);
    float r = __fdiv_rn(p, q);
    return (fabsf(x) < 0.0004f) ? x : r;
}
__device__ __forceinline__ float sigx(float x){
    float t = xla_tanh(__fmul_rn(0.5f, x));
    return __fadd_rn(0.5f, __fmul_rn(0.5f, t));
}

// ---- packed f32x2 helpers ----
__device__ __forceinline__ float2 unpack2(unsigned long long v){
    float2 r;
    asm("mov.b64 {%0, %1}, %2;" : "=f"(r.x), "=f"(r.y) : "l"(v));
    return r;
}
__device__ __forceinline__ void ffma2(unsigned long long& d,
                                      unsigned long long a,
                                      unsigned long long b){
    asm("fma.rn.f32x2 %0, %1, %2, %0;" : "+l"(d) : "l"(a), "l"(b));
}

// de-fma'd 5-state kinetics rhs (matches jnp elementwise)
#define RHS(A,B,C,D,E, dA,dB,dC,dD,dE) {                                 \
    float r1 = __fmul_rn(__fmul_rn(k1p,(A)),(B));                        \
    float r2 = __fmul_rn(k2p,(C));                                       \
    float r3 = __fmul_rn(__fmul_rn(k3p,(C)),(D));                        \
    float r4 = __fmul_rn(k4p,(E));                                       \
    float r5 = __fmul_rn(k5p,(A));                                       \
    dA = __fsub_rn(-r1, r5);                                             \
    dB = __fadd_rn(-r1, r2);                                             \
    dC = __fsub_rn(__fsub_rn(r1, r2), r3);                               \
    dD = __fadd_rn(-r3, r4);                                             \
    dE = __fadd_rn(__fsub_rn(r3, r4), r5); }
#define AXPY(y, c, k) __fadd_rn((y), __fmul_rn((c), (k)))

__global__ void __launch_bounds__(TPB, 1) kin_rnn_kernel(
    const float* __restrict__ y0,      // (512,3)
    const float* __restrict__ u_seq,   // (512,512,3)
    const float* __restrict__ dt_seq,  // (512,512)
    const float* __restrict__ y_seq,   // (512,512,3)
    const float* __restrict__ W_lift,  // (32,6)
    const float* __restrict__ b_lift,  // (32)
    const float* __restrict__ W_ih,    // (384,32)
    const float* __restrict__ W_hh,    // (384,128)
    const float* __restrict__ b_ih,    // (384)
    const float* __restrict__ b_hh,    // (384)
    const float* __restrict__ W_head,  // (5,128)
    const float* __restrict__ b_head,  // (5)
    const float* __restrict__ Jm,      // (3,3)
    float* __restrict__ out)
{
    extern __shared__ float smem[];
    const int tid  = threadIdx.x;
    const int lane = tid & 31;
    const int wid  = tid >> 5;

    ulonglong2* sWhh = (ulonglong2*)(smem + OFF_WHH);   // [j4*384 + row]
    float* sH = smem + OFF_H;

    const bool isDot = (tid >= 128);
    const int  d     = tid - 128;      // dot thread id 0..127; owns rows d, d+128, d+256

    // ---- init: W_hh into pair-layout shared (coalesced global read) ----
    {
        const ulonglong2* src = (const ulonglong2*)W_hh;   // row-major, 32 ull2 per row
        for (int idx = tid; idx < NROW * 32; idx += TPB) {
            int rowg = idx >> 5;       // row
            int j4   = idx & 31;
            sWhh[j4 * NROW + rowg] = src[idx];
        }
    }
    for (int p = tid; p < 1024; p += TPB) sH[p] = 0.f;

    // ---- per-role constants ----
    unsigned long long wih0[16], wih1[16], wih2[16];  // dot: rows d, d+128, d+256 of W_ih
    float bihr=0, bihz=0, bihn=0, bhhr=0, bhhz=0, bhhn=0;
    float wl0=0,wl1=0,wl2=0,wl3=0,wl4=0,wl5=0, blf=0;
    float whd[20];
    float bhsel = 0.f;
    float J00=0,J01=0,J02=0,J10=0,J11=0,J12=0,J20=0,J21=0,J22=0;
    float yA=0,yB=0,yC=0,yD=0,yE=0;
    float uc0=0,uc1=0,uc2=0,dtc=0, up0=0,up1=0,up2=0,dtp=0;
    float tf0=0,tf1=0,tf2=0;
    const float* gu = nullptr; const float* gdt = nullptr; const float* gy = nullptr;
    float* yo = nullptr; float* to = nullptr;

    if (isDot) {
        const ulonglong2* s0 = (const ulonglong2*)(W_ih + d * LN);
        const ulonglong2* s1 = (const ulonglong2*)(W_ih + (d + 128) * LN);
        const ulonglong2* s2 = (const ulonglong2*)(W_ih + (d + 256) * LN);
#pragma unroll
        for (int j = 0; j < 8; j++) {
            ulonglong2 v0 = s0[j]; wih0[2*j] = v0.x; wih0[2*j+1] = v0.y;
            ulonglong2 v1 = s1[j]; wih1[2*j] = v1.x; wih1[2*j+1] = v1.y;
            ulonglong2 v2 = s2[j]; wih2[2*j] = v2.x; wih2[2*j+1] = v2.y;
        }
        bihr = b_ih[d]; bihz = b_ih[128 + d]; bihn = b_ih[256 + d];
        bhhr = b_hh[d]; bhhz = b_hh[128 + d]; bhhn = b_hh[256 + d];
    } else {
        const int g = wid;                        // 0..3
        const int b = blockIdx.x * GB + g;
        wl0 = W_lift[lane*6+0]; wl1 = W_lift[lane*6+1]; wl2 = W_lift[lane*6+2];
        wl3 = W_lift[lane*6+3]; wl4 = W_lift[lane*6+4]; wl5 = W_lift[lane*6+5];
        blf = b_lift[lane];
#pragma unroll
        for (int j = 0; j < 5; j++)
#pragma unroll
            for (int c = 0; c < 4; c++) whd[j*4+c] = W_head[j*HN + lane*4 + c];
        bhsel = b_head[(lane < 5) ? lane : 0];
        J00 = Jm[0]; J01 = Jm[1]; J02 = Jm[2];
        J10 = Jm[3]; J11 = Jm[4]; J12 = Jm[5];
        J20 = Jm[6]; J21 = Jm[7]; J22 = Jm[8];
        yA = y0[b*3+0]; yC = y0[b*3+1]; yE = y0[b*3+2]; yB = 0.f; yD = 0.f;
        gu = u_seq + (size_t)b * NK * 3;
        gdt = dt_seq + (size_t)b * NK;
        gy  = y_seq + (size_t)b * NK * 3;
        yo  = out + (size_t)b * NK * 3;
        to  = out + (size_t)NBATCH * NK * 3 + (size_t)b * NK * 5;
        uc0 = gu[0]; uc1 = gu[1]; uc2 = gu[2]; dtc = gdt[0];
    }
    __syncthreads();

    // batch-warp tail: theta_{kout} + y_jump + RK4_{kout} + outputs_{kout}
    auto tail = [&](int hb, int kout) {
        const int g = wid;
        float4 h4 = ((const float4*)sH)[(hb*32 + lane)*4 + g];
        float t0 = __fmul_rn(whd[0],  h4.x); t0 = fmaf(whd[1],  h4.y, t0);
        t0 = fmaf(whd[2],  h4.z, t0);        t0 = fmaf(whd[3],  h4.w, t0);
        float t1 = __fmul_rn(whd[4],  h4.x); t1 = fmaf(whd[5],  h4.y, t1);
        t1 = fmaf(whd[6],  h4.z, t1);        t1 = fmaf(whd[7],  h4.w, t1);
        float t2 = __fmul_rn(whd[8],  h4.x); t2 = fmaf(whd[9],  h4.y, t2);
        t2 = fmaf(whd[10], h4.z, t2);        t2 = fmaf(whd[11], h4.w, t2);
        float t3 = __fmul_rn(whd[12], h4.x); t3 = fmaf(whd[13], h4.y, t3);
        t3 = fmaf(whd[14], h4.z, t3);        t3 = fmaf(whd[15], h4.w, t3);
        float t4 = __fmul_rn(whd[16], h4.x); t4 = fmaf(whd[17], h4.y, t4);
        t4 = fmaf(whd[18], h4.z, t4);        t4 = fmaf(whd[19], h4.w, t4);
#pragma unroll
        for (int m = 16; m >= 1; m >>= 1) {
            t0 = __fadd_rn(t0, __shfl_xor_sync(0xffffffffu, t0, m));
            t1 = __fadd_rn(t1, __shfl_xor_sync(0xffffffffu, t1, m));
            t2 = __fadd_rn(t2, __shfl_xor_sync(0xffffffffu, t2, m));
            t3 = __fadd_rn(t3, __shfl_xor_sync(0xffffffffu, t3, m));
            t4 = __fadd_rn(t4, __shfl_xor_sync(0xffffffffu, t4, m));
        }
        float tsel = (lane == 0) ? t0 : (lane == 1) ? t1 :
                     (lane == 2) ? t2 : (lane == 3) ? t3 : t4;
        float ssel = sigx(__fadd_rn(tsel, bhsel));
        float ksel = __fadd_rn(THETA_LO, __fmul_rn(THETA_RANGE, ssel));
        float k1p = __shfl_sync(0xffffffffu, ksel, 0);
        float k2p = __shfl_sync(0xffffffffu, ksel, 1);
        float k3p = __shfl_sync(0xffffffffu, ksel, 2);
        float k4p = __shfl_sync(0xffffffffu, ksel, 3);
        float k5p = __shfl_sync(0xffffffffu, ksel, 4);

        {
            float jA = __fmul_rn(up0, J00); jA = fmaf(up1, J10, jA); jA = fmaf(up2, J20, jA);
            float jC = __fmul_rn(up0, J01); jC = fmaf(up1, J11, jC); jC = fmaf(up2, J21, jC);
            float jE = __fmul_rn(up0, J02); jE = fmaf(up1, J12, jE); jE = fmaf(up2, J22, jE);
            yA = __fadd_rn(yA, jA); yC = __fadd_rn(yC, jC); yE = __fadd_rn(yE, jE);
        }
        float hstep = dtp;
        float hh = __fmul_rn(0.5f, hstep);
        float d1A,d1B,d1C,d1D,d1E, d2A,d2B,d2C,d2D,d2E;
        float d3A,d3B,d3C,d3D,d3E, d4A,d4B,d4C,d4D,d4E;
        RHS(yA, yB, yC, yD, yE, d1A, d1B, d1C, d1D, d1E);
        {
            float tA = AXPY(yA, hh, d1A), tB = AXPY(yB, hh, d1B), tC = AXPY(yC, hh, d1C);
            float tD = AXPY(yD, hh, d1D), tE = AXPY(yE, hh, d1E);
            RHS(tA, tB, tC, tD, tE, d2A, d2B, d2C, d2D, d2E);
        }
        {
            float tA = AXPY(yA, hh, d2A), tB = AXPY(yB, hh, d2B), tC = AXPY(yC, hh, d2C);
            float tD = AXPY(yD, hh, d2D), tE = AXPY(yE, hh, d2E);
            RHS(tA, tB, tC, tD, tE, d3A, d3B, d3C, d3D, d3E);
        }
        {
            float tA = AXPY(yA, hstep, d3A), tB = AXPY(yB, hstep, d3B), tC = AXPY(yC, hstep, d3C);
            float tD = AXPY(yD, hstep, d3D), tE = AXPY(yE, hstep, d3E);
            RHS(tA, tB, tC, tD, tE, d4A, d4B, d4C, d4D, d4E);
        }
        float s6 = __fdiv_rn(hstep, 6.0f);
        #define RKSUM(d1,d2,d3,d4) \
            __fadd_rn(__fadd_rn(__fadd_rn((d1), __fmul_rn(2.0f,(d2))), __fmul_rn(2.0f,(d3))), (d4))
        yA = fmaxf(AXPY(yA, s6, RKSUM(d1A,d2A,d3A,d4A)), 0.f);
        yB = fmaxf(AXPY(yB, s6, RKSUM(d1B,d2B,d3B,d4B)), 0.f);
        yC = fmaxf(AXPY(yC, s6, RKSUM(d1C,d2C,d3C,d4C)), 0.f);
        yD = fmaxf(AXPY(yD, s6, RKSUM(d1D,d2D,d3D,d4D)), 0.f);
        yE = fmaxf(AXPY(yE, s6, RKSUM(d1E,d2E,d3E,d4E)), 0.f);
        #undef RKSUM

        if (lane < 3) {
            float ysel = (lane == 0) ? yA : ((lane == 1) ? yC : yE);
            yo[kout * 3 + lane] = ysel;
        }
        if (lane < 5) to[kout * 5 + lane] = ksel;
    };

    for (int k = 0; k < NK; k++) {
        const int hb = k & 1;
        unsigned long long ghr[4], ghz[4], ghn[4];
        if (isDot) {
            // ---- gh dot: 3 rows per thread, h broadcast amortized over 24 FFMA2 ----
#pragma unroll
            for (int g = 0; g < 4; g++) { ghr[g] = 0ull; ghz[g] = 0ull; ghn[g] = 0ull; }
            const ulonglong2* sHb = (const ulonglong2*)sH + hb * 128;
#pragma unroll 8
            for (int j4 = 0; j4 < 32; j4++) {
                ulonglong2 wr = sWhh[j4 * NROW + d];
                ulonglong2 wz = sWhh[j4 * NROW + 128 + d];
                ulonglong2 wn = sWhh[j4 * NROW + 256 + d];
#pragma unroll
                for (int g = 0; g < 4; g++) {
                    ulonglong2 hv = sHb[j4 * 4 + g];
                    ffma2(ghr[g], wr.x, hv.x); ffma2(ghr[g], wr.y, hv.y);
                    ffma2(ghz[g], wz.x, hv.x); ffma2(ghz[g], wz.y, hv.y);
                    ffma2(ghn[g], wn.x, hv.x); ffma2(ghn[g], wn.y, hv.y);
                }
            }
        } else {
            // ---- batch warp: finish step k-1, then lift for step k ----
            if (k > 0) tail(hb, k - 1);
            bool flag = (k > 0) && ((k % 50) == 0);
            float yi0 = flag ? tf0 : yA;
            float yi1 = flag ? tf1 : yC;
            float yi2 = flag ? tf2 : yE;
            float lv = __fmul_rn(wl0, uc0);
            lv = fmaf(wl1, uc1, lv);
            lv = fmaf(wl2, uc2, lv);
            lv = fmaf(wl3, yi0, lv);
            lv = fmaf(wl4, yi1, lv);
            lv = fmaf(wl5, yi2, lv);
            lv = __fadd_rn(lv, blf);
            lv = __fmul_rn(lv, sigx(lv));
            smem[OFF_LF + ((lane >> 2) * 4 + wid) * 4 + (lane & 3)] = lv;
            up0 = uc0; up1 = uc1; up2 = uc2; dtp = dtc;
        }
        __syncthreads();   // A: lift ready (and tail done reading buf hb)

        if (isDot) {
            // ---- gx dot (W_ih in regs, lift broadcast) ----
            unsigned long long gxr[4], gxz[4], gxn[4];
#pragma unroll
            for (int g = 0; g < 4; g++) { gxr[g] = 0ull; gxz[g] = 0ull; gxn[g] = 0ull; }
            const ulonglong2* sLf2 = (const ulonglong2*)(smem + OFF_LF);
#pragma unroll
            for (int j4 = 0; j4 < 8; j4++) {
#pragma unroll
                for (int g = 0; g < 4; g++) {
                    ulonglong2 l = sLf2[j4 * 4 + g];
                    ffma2(gxr[g], wih0[2*j4], l.x); ffma2(gxr[g], wih0[2*j4+1], l.y);
                    ffma2(gxz[g], wih1[2*j4], l.x); ffma2(gxz[g], wih1[2*j4+1], l.y);
                    ffma2(gxn[g], wih2[2*j4], l.x); ffma2(gxn[g], wih2[2*j4+1], l.y);
                }
            }
            // ---- gates + GRU update, all local to this thread (unit d, 4 batches) ----
#pragma unroll
            for (int g = 0; g < 4; g++) {
                float2 pr = unpack2(ghr[g]);
                float2 pz = unpack2(ghz[g]);
                float2 pn = unpack2(ghn[g]);
                float2 qr = unpack2(gxr[g]);
                float2 qz = unpack2(gxz[g]);
                float2 qn = unpack2(gxn[g]);
                float ghr_s = __fadd_rn(__fadd_rn(pr.x, pr.y), bhhr);
                float ghz_s = __fadd_rn(__fadd_rn(pz.x, pz.y), bhhz);
                float ghn_s = __fadd_rn(__fadd_rn(pn.x, pn.y), bhhn);
                float gxr_s = __fadd_rn(__fadd_rn(qr.x, qr.y), bihr);
                float gxz_s = __fadd_rn(__fadd_rn(qz.x, qz.y), bihz);
                float gxn_s = __fadd_rn(__fadd_rn(qn.x, qn.y), bihn);
                float r = sigx(__fadd_rn(gxr_s, ghr_s));
                float z = sigx(__fadd_rn(gxz_s, ghz_s));
                float n = xla_tanh(__fadd_rn(gxn_s, __fmul_rn(r, ghn_s)));
                float hold = sH[HIDX(hb, d, g)];
                float hnew = __fadd_rn(__fmul_rn(__fsub_rn(1.0f, z), n), __fmul_rn(z, hold));
                sH[HIDX(1 - hb, d, g)] = hnew;
            }
        } else {
            // ---- prefetch next step inputs ----
            if (k + 1 < NK) {
                uc0 = gu[3*(k+1)]; uc1 = gu[3*(k+1)+1]; uc2 = gu[3*(k+1)+2];
                dtc = gdt[k+1];
                if (((k + 1) % 50) == 0) { tf0 = gy[3*k]; tf1 = gy[3*k+1]; tf2 = gy[3*k+2]; }
            }
        }
        __syncthreads();   // C: h_{k+1} ready
    }

    // epilogue: step 511 tail (h_512 sits in buffer 0)
    if (!isDot) tail(0, NK - 1);
}

extern "C" void kernel_launch(void* const* d_in, const int* in_sizes, int n_in,
                              void* d_out, int out_size) {
    const float* y0     = (const float*)d_in[0];
    const float* u_seq  = (const float*)d_in[1];
    const float* dt_seq = (const float*)d_in[2];
    const float* y_seq  = (const float*)d_in[3];
    const float* W_lift = (const float*)d_in[4];
    const float* b_lift = (const float*)d_in[5];
    const float* W_ih   = (const float*)d_in[6];
    const float* W_hh   = (const float*)d_in[7];
    const float* b_ih   = (const float*)d_in[8];
    const float* b_hh   = (const float*)d_in[9];
    const float* W_head = (const float*)d_in[10];
    const float* b_head = (const float*)d_in[11];
    const float* Jm     = (const float*)d_in[12];
    float* out = (float*)d_out;

    const int smemBytes = SMEM_FLOATS * 4;   // 201216 B
    cudaFuncSetAttribute(kin_rnn_kernel,
                         cudaFuncAttributeMaxDynamicSharedMemorySize, smemBytes);
    // 128 blocks x 256 threads: warps 0-3 batch warps (4 batches),
    // warps 4-7: 128 dot threads, each owning gate rows d, d+128, d+256.
    kin_rnn_kernel<<<NBATCH / GB, TPB, smemBytes>>>(
        y0, u_seq, dt_seq, y_seq, W_lift, b_lift,
        W_ih, W_hh, b_ih, b_hh, W_head, b_head, Jm, out);
}